// round 13
// baseline (speedup 1.0000x reference)
#include <cuda_runtime.h>
#include <cuda_fp16.h>
#include <math.h>

#define EE 1024
#define HN 16
#define HDIM 64
#define DI 64
#define BB 2
#define TT 2048
#define NROW (BB*TT)   // 4096
#define G3 192
#define KP 960         // proj K
#define NCHK 8         // GRU pipeline chunks
#define TCH (TT/NCHK)  // 256 steps per chunk

// ---------------- scratch (static device memory) ---------------------------
__device__ __half g_proj2[NROW*KP];     // half, shared by q/k
__device__ float g_xw_q[NROW*G3];
__device__ float g_xw_k[NROW*G3];
__device__ float g_pos_q[NROW*DI];
__device__ float g_pos_k[NROW*DI];
__device__ float g_hstate[4*DI];        // GRU h carry between chunk kernels
__device__ float g_qpre[NROW*EE];
__device__ float g_kpre[NROW*EE];
__device__ __half g_qh2[BB*HN*TT*HDIM]; // [bh][t][d], pre-scaled 0.25*log2e
__device__ __half g_kh2[BB*HN*TT*HDIM];
__device__ __half g_vh2[BB*HN*TT*HDIM];
__device__ __half g_vT2[BB*HN*HDIM*TT]; // [bh][d][t]
__device__ __half g_ao2[NROW*EE];       // attention out (half)
__device__ __half g_wq2[EE*EE];         // half weights
__device__ __half g_wk2[EE*EE];
__device__ __half g_wo2[EE*EE];

__device__ __forceinline__ float ex2f(float x) {
    float y;
    asm("ex2.approx.f32 %0, %1;" : "=f"(y) : "f"(x));
    return y;
}
__device__ __forceinline__ float tanhf_fast(float x) {
    float y;
    asm("tanh.approx.f32 %0, %1;" : "=f"(y) : "f"(x));
    return y;
}
#define LOG2E_F 1.44269504f
#define QSCALE (0.25f*LOG2E_F)

#define MMA_F16(d, a, b0, b1) \
    asm volatile("mma.sync.aligned.m16n8k16.row.col.f32.f16.f16.f32 " \
        "{%0,%1,%2,%3},{%4,%5,%6,%7},{%8,%9},{%0,%1,%2,%3};" \
        : "+f"((d)[0]), "+f"((d)[1]), "+f"((d)[2]), "+f"((d)[3]) \
        : "r"((a)[0]), "r"((a)[1]), "r"((a)[2]), "r"((a)[3]), "r"(b0), "r"(b1))

#define CPA16(dst_u32, src) \
    asm volatile("cp.async.cg.shared.global [%0], [%1], 16;" :: "r"(dst_u32), "l"(src))
#define CPCOMMIT() asm volatile("cp.async.commit_group;")
#define CPWAIT(n)  asm volatile("cp.async.wait_group %0;" :: "n"(n))

// packed f32x2 helpers
__device__ __forceinline__ unsigned long long packf2(float x, float y) {
    unsigned long long p;
    asm("mov.b64 %0, {%1, %2};" : "=l"(p) : "f"(x), "f"(y));
    return p;
}
__device__ __forceinline__ void unpackf2(unsigned long long p, float& x, float& y) {
    asm("mov.b64 {%0, %1}, %2;" : "=f"(x), "=f"(y) : "l"(p));
}
#define FMA2(acc, a, b) \
    asm("fma.rn.f32x2 %0, %1, %2, %0;" : "+l"(acc) : "l"(a), "l"(b))

// ---------------- weight convert to half ------------------------------------
__global__ void __launch_bounds__(256) hconv_kernel(
    const float* __restrict__ qw, const float* __restrict__ kw,
    const float* __restrict__ ow)
{
    const float* src = blockIdx.y == 0 ? qw : (blockIdx.y == 1 ? kw : ow);
    __half* dst = blockIdx.y == 0 ? g_wq2 : (blockIdx.y == 1 ? g_wk2 : g_wo2);
    long i = ((long)blockIdx.x*256 + threadIdx.x)*4;
    float4 v = *(const float4*)(src + i);
    __half2 h01 = __floats2half2_rn(v.x, v.y);
    __half2 h23 = __floats2half2_rn(v.z, v.w);
    uint2 pk;
    pk.x = *(unsigned*)&h01;
    pk.y = *(unsigned*)&h23;
    *(uint2*)(dst + i) = pk;
}

// ---------------- prep_xw: pool(x) @ wih^T for both paths ------------------
__global__ void __launch_bounds__(256) prep_xw_kernel(
    const float* __restrict__ x,
    const float* __restrict__ qwih, const float* __restrict__ kwih)
{
    __shared__ float xs[DI];
    int row = blockIdx.x;
    int tid = threadIdx.x;
    if (tid < DI) {
        const float* xp = x + (long)row*EE + tid*16;
        float s = 0.f;
        #pragma unroll
        for (int i = 0; i < 4; i++) {
            float4 v = ((const float4*)xp)[i];
            s += (v.x + v.y) + (v.z + v.w);
        }
        xs[tid] = s * (1.f/16.f);
    }
    __syncthreads();

    for (int idx = tid; idx < 2*G3; idx += 256) {
        int path = idx / G3, g = idx - path*G3;
        const float* w = (path ? kwih : qwih) + g*DI;
        float a0=0.f, a1=0.f, a2=0.f, a3=0.f;
        #pragma unroll
        for (int d = 0; d < DI; d += 4) {
            a0 += xs[d+0]*w[d+0];
            a1 += xs[d+1]*w[d+1];
            a2 += xs[d+2]*w[d+2];
            a3 += xs[d+3]*w[d+3];
        }
        float acc = (a0+a1)+(a2+a3);
        (path ? g_xw_k : g_xw_q)[(long)row*G3 + g] = acc;
    }
}

// ---------------- prep_main: v = silu(x)*emb (half), proj pool (half) ------
__global__ void __launch_bounds__(256) prep_main_kernel(
    const float* __restrict__ x, const int* __restrict__ tok,
    const float* __restrict__ vemb)
{
    __shared__ float xsh[EE];
    int row = blockIdx.x;
    int tid = threadIdx.x;
    int b = row >> 11, t = row & (TT-1);

    ((float4*)xsh)[tid] = ((const float4*)(x + (long)row*EE))[tid];
    __syncthreads();

    int tk = tok[row];
    const float* ve = vemb + (long)tk*EE;
    for (int c = tid; c < EE; c += 256) {
        float xc = xsh[c];
        float sg = fmaf(0.5f, tanhf_fast(0.5f*xc), 0.5f);
        float val = xc * sg * ve[c];
        int h = c >> 6, d = c & 63;
        g_vh2[((long)(b*HN + h)*TT + t)*HDIM + d] = __float2half_rn(val);
    }

    for (int j = tid; j < KP; j += 256) {
        int s0 = (j*16)/15;
        int e0 = ((j+1)*16 + 14)/15;
        float s = 0.f;
        for (int c = s0; c < e0; c++) s += xsh[c];
        s *= 1.f/(float)(e0 - s0);
        g_proj2[(long)row*KP + j] = __float2half_rn(s);
    }
}

// ---------------- vt: transpose V [bh][t][d] -> [bh][d][t] ------------------
__global__ void __launch_bounds__(256) vt_kernel()
{
    __shared__ __half T[64*72];
    int bh = blockIdx.y;
    int t0 = blockIdx.x * 64;
    int tid = threadIdx.x;

    #pragma unroll
    for (int i = 0; i < 2; i++) {
        int f = tid + i*256;
        int rr = f >> 3;
        int c8 = (f & 7) * 8;
        uint4 v = *(const uint4*)(g_vh2 + ((long)bh*TT + t0 + rr)*HDIM + c8);
        const __half* hv = (const __half*)&v;
        #pragma unroll
        for (int j = 0; j < 8; j++)
            T[(c8 + j)*72 + rr] = hv[j];
    }
    __syncthreads();
    #pragma unroll
    for (int i = 0; i < 2; i++) {
        int f = tid + i*256;
        int rr = f >> 3;
        int c8 = (f & 7) * 8;
        uint4 v = *(const uint4*)(T + rr*72 + c8);
        *(uint4*)(g_vT2 + ((long)bh*HDIM + rr)*TT + t0 + c8) = v;
    }
}

// ---------------- GRU chunk kernel: 256 steps, h carried via g_hstate ------
#define GRU_SPC 32
#define GRU_CHUNK (GRU_SPC*G3)          // 6144 floats
#define GRU_PAD_SMEM 196608             // 192KB: keeps other blocks off these SMs

__global__ void __launch_bounds__(128, 1) gru_kernel(
    const float* __restrict__ qwhh, const float* __restrict__ kwhh, int chunk)
{
    extern __shared__ float gsm[];      // only first 2*GRU_CHUNK used
    __shared__ float hbuf[2][DI];
    int path = blockIdx.x >> 1;
    int b = blockIdx.x & 1;
    int tid = threadIdx.x;
    int j = tid >> 1;
    int half = tid & 1;
    const float* W = (path ? kwhh : qwhh);
    const float* xw = (path ? g_xw_k : g_xw_q) + (long)b*TT*G3 + (long)chunk*TCH*G3;
    float* pos = (path ? g_pos_k : g_pos_q) + (long)b*TT*DI + (long)chunk*TCH*DI;

    unsigned long long wr[16], wz[16], wn[16];
    {
        const float* pr = W + (long)j*DI + half*32;
        const float* pz = W + (long)(64+j)*DI + half*32;
        const float* pn = W + (long)(128+j)*DI + half*32;
        #pragma unroll
        for (int i = 0; i < 16; i++) {
            wr[i] = packf2(pr[2*i], pr[2*i+1]);
            wz[i] = packf2(pz[2*i], pz[2*i+1]);
            wn[i] = packf2(pn[2*i], pn[2*i+1]);
        }
    }

    float h0 = (chunk == 0) ? 0.f : g_hstate[blockIdx.x*DI + j];
    if (tid < DI)
        hbuf[0][tid] = (chunk == 0) ? 0.f : g_hstate[blockIdx.x*DI + tid];
    float hprev = h0;

    #pragma unroll
    for (int i = 0; i < 12; i++) {
        int f = tid + i*128;
        unsigned d = (unsigned)__cvta_generic_to_shared(gsm + f*4);
        CPA16(d, xw + f*4);
    }
    CPCOMMIT();

    const int NC = TCH / GRU_SPC;   // 8
    for (int c = 0; c < NC; c++) {
        if (c + 1 < NC) {
            const float* src = xw + (long)(c+1)*GRU_CHUNK;
            float* dstb = gsm + ((c+1) & 1)*GRU_CHUNK;
            #pragma unroll
            for (int i = 0; i < 12; i++) {
                int f = tid + i*128;
                unsigned d = (unsigned)__cvta_generic_to_shared(dstb + f*4);
                CPA16(d, src + f*4);
            }
            CPCOMMIT();
            CPWAIT(1);
        } else {
            CPWAIT(0);
        }
        __syncthreads();

        const float* xc = gsm + (c & 1)*GRU_CHUNK;
        for (int s = 0; s < GRU_SPC; s++) {
            int t = c*GRU_SPC + s;
            int cur = t & 1, nxt = cur ^ 1;

            float xr = xc[s*G3 + j];
            float xz = xc[s*G3 + 64 + j];
            float xn = xc[s*G3 + 128 + j];

            const float4* hb4 = (const float4*)(hbuf[cur] + half*32);
            unsigned long long ar[4] = {0,0,0,0};
            unsigned long long az[4] = {0,0,0,0};
            unsigned long long an[4] = {0,0,0,0};
            #pragma unroll
            for (int i = 0; i < 8; i++) {
                float4 hv = hb4[i];
                unsigned long long h01 = packf2(hv.x, hv.y);
                unsigned long long h23 = packf2(hv.z, hv.w);
                int e = (i & 1) << 1;
                FMA2(ar[e],   h01, wr[2*i]);  FMA2(ar[e+1], h23, wr[2*i+1]);
                FMA2(az[e],   h01, wz[2*i]);  FMA2(az[e+1], h23, wz[2*i+1]);
                FMA2(an[e],   h01, wn[2*i]);  FMA2(an[e+1], h23, wn[2*i+1]);
            }
            float a0,a1,a2,a3,b0,b1,b2,b3;
            unpackf2(ar[0],a0,a1); unpackf2(ar[1],a2,a3);
            unpackf2(ar[2],b0,b1); unpackf2(ar[3],b2,b3);
            float pr = ((a0+a1)+(a2+a3)) + ((b0+b1)+(b2+b3));
            unpackf2(az[0],a0,a1); unpackf2(az[1],a2,a3);
            unpackf2(az[2],b0,b1); unpackf2(az[3],b2,b3);
            float pz = ((a0+a1)+(a2+a3)) + ((b0+b1)+(b2+b3));
            unpackf2(an[0],a0,a1); unpackf2(an[1],a2,a3);
            unpackf2(an[2],b0,b1); unpackf2(an[3],b2,b3);
            float pn = ((a0+a1)+(a2+a3)) + ((b0+b1)+(b2+b3));

            pr += __shfl_xor_sync(0xffffffffu, pr, 1);
            pz += __shfl_xor_sync(0xffffffffu, pz, 1);
            pn += __shfl_xor_sync(0xffffffffu, pn, 1);

            float r = fmaf(0.5f, tanhf_fast(0.5f*(pr + xr)), 0.5f);
            float z = fmaf(0.5f, tanhf_fast(0.5f*(pz + xz)), 0.5f);
            float n = tanhf_fast(fmaf(r, pn, xn));
            float hn = fmaf(z, hprev - n, n);
            hprev = hn;

            hbuf[nxt][j] = hn;
            if (half == 0) pos[(long)t*DI + j] = hn;
            __syncthreads();
        }
    }

    if (half == 0) g_hstate[blockIdx.x*DI + j] = hprev;
}

// ---------------- fp16 tensor-core GEMM: C = A @ W^T (+res)(+bias) ---------
#define HGS 40
template<bool RES, bool BIAS>
__device__ __forceinline__ void hgemm_body(
    const __half* __restrict__ A, int lda,
    const __half* __restrict__ W, int ldw,
    const float* __restrict__ res, const float* __restrict__ bias,
    float* __restrict__ C, int N, int NK, int m0, int n0)
{
    __shared__ __half As[2][128*HGS];
    __shared__ __half Bs[2][128*HGS];
    int tid = threadIdx.x;
    int wid = tid >> 5, lane = tid & 31;
    int g = lane >> 2, tig = lane & 3;
    int wm = (wid >> 2) * 64, wn = (wid & 3) * 32;
    int lrow = tid >> 1, lc = (tid & 1) * 16;

    const __half* Ap = A + (long)(m0 + lrow)*lda + lc;
    const __half* Wp = W + (long)(n0 + lrow)*ldw + lc;

    uint4 ra0 = *(const uint4*)(Ap);
    uint4 ra1 = *(const uint4*)(Ap + 8);
    uint4 rb0 = *(const uint4*)(Wp);
    uint4 rb1 = *(const uint4*)(Wp + 8);

    float acc[4][4][4] = {};
    int buf = 0;
    for (int kt = 0; kt < NK; kt++) {
        __half* Asb = As[buf];
        __half* Bsb = Bs[buf];
        *(uint4*)(Asb + lrow*HGS + lc) = ra0;
        *(uint4*)(Asb + lrow*HGS + lc + 8) = ra1;
        *(uint4*)(Bsb + lrow*HGS + lc) = rb0;
        *(uint4*)(Bsb + lrow*HGS + lc + 8) = rb1;
        __syncthreads();
        if (kt + 1 < NK) {
            int ko = (kt+1)*32;
            ra0 = *(const uint4*)(Ap + ko);
            ra1 = *(const uint4*)(Ap + ko + 8);
            rb0 = *(const uint4*)(Wp + ko);
            rb1 = *(const uint4*)(Wp + ko + 8);
        }
        #pragma unroll
        for (int kk = 0; kk < 32; kk += 16) {
            unsigned a[4][4], b[4][2];
            #pragma unroll
            for (int mt = 0; mt < 4; mt++) {
                int r = wm + mt*16 + g;
                a[mt][0] = *(const unsigned*)(Asb + r*HGS + kk + 2*tig);
                a[mt][1] = *(const unsigned*)(Asb + (r+8)*HGS + kk + 2*tig);
                a[mt][2] = *(const unsigned*)(Asb + r*HGS + kk + 2*tig + 8);
                a[mt][3] = *(const unsigned*)(Asb + (r+8)*HGS + kk + 2*tig + 8);
            }
            #pragma unroll
            for (int nt = 0; nt < 4; nt++) {
                int r = wn + nt*8 + g;
                b[nt][0] = *(const unsigned*)(Bsb + r*HGS + kk + 2*tig);
                b[nt][1] = *(const unsigned*)(Bsb + r*HGS + kk + 2*tig + 8);
            }
            #pragma unroll
            for (int mt = 0; mt < 4; mt++)
                #pragma unroll
                for (int nt = 0; nt < 4; nt++)
                    MMA_F16(acc[mt][nt], a[mt], b[nt][0], b[nt][1]);
        }
        buf ^= 1;
    }

    #pragma unroll
    for (int mt = 0; mt < 4; mt++) {
        #pragma unroll
        for (int nt = 0; nt < 4; nt++) {
            long r0 = m0 + wm + mt*16 + g;
            long r1 = r0 + 8;
            long cb = n0 + wn + nt*8 + tig*2;
            float v0 = acc[mt][nt][0], v1 = acc[mt][nt][1];
            float v2 = acc[mt][nt][2], v3 = acc[mt][nt][3];
            if (RES) {
                float2 e0 = *(const float2*)(res + r0*N + cb);
                float2 e1 = *(const float2*)(res + r1*N + cb);
                v0 += e0.x; v1 += e0.y; v2 += e1.x; v3 += e1.y;
            }
            if (BIAS) {
                v0 += bias[cb]; v1 += bias[cb+1];
                v2 += bias[cb]; v3 += bias[cb+1];
            }
            *(float2*)(C + r0*N + cb) = make_float2(v0, v1);
            *(float2*)(C + r1*N + cb) = make_float2(v2, v3);
        }
    }
}

__global__ void __launch_bounds__(256) hgemm_qk_kernel(const float* __restrict__ x)
{
    int z = blockIdx.z;
    hgemm_body<true,false>(g_proj2, KP, (z ? g_wk2 : g_wq2) + DI, EE, x, nullptr,
                           z ? g_kpre : g_qpre, EE, KP/32,
                           blockIdx.y*128, blockIdx.x*128);
}

// out-GEMM for one GRU chunk's rows: grid (8, 4); y: b*2 + i (2 M-tiles/batch)
__global__ void __launch_bounds__(256) hgemm_out_kernel(
    const float* __restrict__ bias, float* __restrict__ C, int cch)
{
    int b = blockIdx.y >> 1;
    int m0 = b*TT + cch*TCH + (blockIdx.y & 1)*128;
    hgemm_body<false,true>(g_ao2, EE, g_wo2, EE, nullptr, bias, C, EE, EE/32,
                           m0, blockIdx.x*128);
}

// ---------------- pos small GEMM (chunked): C += pos @ Wpos^T ---------------
// grid (8, 16, 2): per chunk, 2 batches x 256 rows (8 blocks of 32 rows each).
__global__ void __launch_bounds__(256) posgemm_kernel(
    const float* __restrict__ qw, const float* __restrict__ kw, int cch)
{
    int path = blockIdx.z;
    const float* pos = path ? g_pos_k : g_pos_q;
    const float* W = path ? kw : qw;
    float* C = path ? g_kpre : g_qpre;
    __shared__ float Wt[64][132];
    __shared__ float Ps_[32][68];
    int n0 = blockIdx.x * 128;
    int bsel = blockIdx.y >> 3;
    int m0 = bsel*TT + cch*TCH + (blockIdx.y & 7)*32;
    int tid = threadIdx.x;

    for (int i = tid; i < 128*16; i += 256) {
        int r = i >> 4, c4 = (i & 15)*4;
        float4 v = *(const float4*)(W + (long)(n0 + r)*EE + c4);
        Wt[c4+0][r] = v.x; Wt[c4+1][r] = v.y; Wt[c4+2][r] = v.z; Wt[c4+3][r] = v.w;
    }
    for (int i = tid; i < 32*16; i += 256) {
        int r = i >> 4, c4 = (i & 15)*4;
        *(float4*)&Ps_[r][c4] = *(const float4*)(pos + (long)(m0 + r)*DI + c4);
    }
    __syncthreads();

    int tx = tid & 15, ty = tid >> 4;
    int r0 = ty*2, c0 = tx*8;
    float acc[2][8] = {};
    #pragma unroll
    for (int k = 0; k < 64; k++) {
        float p0 = Ps_[r0][k], p1 = Ps_[r0+1][k];
        float4 w0 = *(float4*)&Wt[k][c0];
        float4 w1 = *(float4*)&Wt[k][c0+4];
        acc[0][0] += p0*w0.x; acc[0][1] += p0*w0.y; acc[0][2] += p0*w0.z; acc[0][3] += p0*w0.w;
        acc[0][4] += p0*w1.x; acc[0][5] += p0*w1.y; acc[0][6] += p0*w1.z; acc[0][7] += p0*w1.w;
        acc[1][0] += p1*w0.x; acc[1][1] += p1*w0.y; acc[1][2] += p1*w0.z; acc[1][3] += p1*w0.w;
        acc[1][4] += p1*w1.x; acc[1][5] += p1*w1.y; acc[1][6] += p1*w1.z; acc[1][7] += p1*w1.w;
    }
    #pragma unroll
    for (int i = 0; i < 2; i++) {
        long m = m0 + r0 + i;
        #pragma unroll
        for (int j = 0; j < 8; j += 4) {
            float4 old = *(float4*)(C + m*EE + n0 + c0 + j);
            old.x += acc[i][j]; old.y += acc[i][j+1];
            old.z += acc[i][j+2]; old.w += acc[i][j+3];
            *(float4*)(C + m*EE + n0 + c0 + j) = old;
        }
    }
}

// ---------------- LayerNorm (chunked) -> head-major half --------------------
// grid 1024: path(2) x batch(2) x 256 rows of chunk c.
__global__ void __launch_bounds__(256) ln_kernel(
    const float* __restrict__ wq, const float* __restrict__ bq,
    const float* __restrict__ wk, const float* __restrict__ bk, int cch)
{
    int idx = blockIdx.x;
    int path = idx >> 9;
    int local = idx & 511;
    int b = local >> 8;
    int t = cch*TCH + (local & 255);
    int row = b*TT + t;
    const float* src = (path ? g_kpre : g_qpre) + (long)row*EE;
    const float* w = path ? wk : wq;
    const float* bb = path ? bk : bq;
    __half* dst = path ? g_kh2 : g_qh2;
    float oscale = path ? 1.f : QSCALE;
    int tid = threadIdx.x;

    float4 v = ((const float4*)src)[tid];
    float s  = v.x + v.y + v.z + v.w;
    float sq = v.x*v.x + v.y*v.y + v.z*v.z + v.w*v.w;
    #pragma unroll
    for (int o = 16; o; o >>= 1) {
        s  += __shfl_xor_sync(0xffffffffu, s,  o);
        sq += __shfl_xor_sync(0xffffffffu, sq, o);
    }
    __shared__ float ss[8], sqs[8];
    __shared__ float mu_s, r_s;
    if ((tid & 31) == 0) { ss[tid >> 5] = s; sqs[tid >> 5] = sq; }
    __syncthreads();
    if (tid == 0) {
        float S = 0.f, SQ = 0.f;
        #pragma unroll
        for (int i = 0; i < 8; i++) { S += ss[i]; SQ += sqs[i]; }
        float mu = S * (1.f/EE);
        float var = SQ * (1.f/EE) - mu*mu;
        mu_s = mu;
        r_s = rsqrtf(var + 1e-5f);
    }
    __syncthreads();
    float mu = mu_s, r = r_s;
    int c0 = tid * 4;
    int h = c0 >> 6, d = c0 & 63;
    float o0 = ((v.x - mu)*r*w[c0+0] + bb[c0+0]) * oscale;
    float o1 = ((v.y - mu)*r*w[c0+1] + bb[c0+1]) * oscale;
    float o2 = ((v.z - mu)*r*w[c0+2] + bb[c0+2]) * oscale;
    float o3 = ((v.w - mu)*r*w[c0+3] + bb[c0+3]) * oscale;
    __half2 h01 = __floats2half2_rn(o0, o1);
    __half2 h23 = __floats2half2_rn(o2, o3);
    uint2 pk;
    pk.x = *(unsigned*)&h01;
    pk.y = *(unsigned*)&h23;
    *(uint2*)&dst[((long)(b*HN + h)*TT + t)*HDIM + d] = pk;
}

// ---------------- fp16 flash attention (chunked q-blocks) -------------------
#define HS 72
#define AKVH (64*HS*2)
#define APSH (2*AKVH)
#define ATT5_SMEM ((APSH + 128*HS)*2)  // 55296 bytes

__device__ __forceinline__ void attn5_issue(
    __half* sm, int buf, int s0, int tid,
    const __half* kb, const __half* vtb)
{
    __half* K = sm + buf*AKVH;
    __half* V = K + 64*HS;
    #pragma unroll
    for (int i = 0; i < 2; i++) {
        int f = tid + i*256;
        int rr = f >> 3;
        int c = (f & 7) * 8;
        unsigned kd = (unsigned)__cvta_generic_to_shared(K + rr*HS + c);
        CPA16(kd, kb + (long)(s0 + rr)*HDIM + c);
        unsigned vd = (unsigned)__cvta_generic_to_shared(V + rr*HS + c);
        CPA16(vd, vtb + (long)rr*TT + s0 + c);
    }
}

__global__ void __launch_bounds__(256, 2) attn5_kernel(int qb_base)
{
    extern __shared__ __half smh[];
    __half* Qs = smh;
    __half* Ps = smh + APSH;

    int bh = blockIdx.y;
    int qblk = qb_base + (int)gridDim.x - 1 - (int)blockIdx.x;  // longest first
    int qr0 = qblk * 128;
    int tid = threadIdx.x;
    int wid = tid >> 5, lane = tid & 31;
    int g = lane >> 2, tig = lane & 3;
    int r0 = wid * 16;

    const __half* qbase = g_qh2 + (long)bh*TT*HDIM;
    const __half* kbase = g_kh2 + (long)bh*TT*HDIM;
    const __half* vtbase = g_vT2 + (long)bh*HDIM*TT;

    #pragma unroll
    for (int i = 0; i < 4; i++) {
        int f = tid + i*256;
        int rr = f >> 3;
        int c = (f & 7) * 8;
        *(uint4*)(Qs + rr*HS + c) =
            *(const uint4*)(qbase + (long)(qr0 + rr)*HDIM + c);
    }
    __syncthreads();
    unsigned qf[4][4];
    #pragma unroll
    for (int k = 0; k < 4; k++) {
        int kb = k*16;
        qf[k][0] = *(const unsigned*)(Qs + (r0+g)*HS + kb + 2*tig);
        qf[k][1] = *(const unsigned*)(Qs + (r0+g+8)*HS + kb + 2*tig);
        qf[k][2] = *(const unsigned*)(Qs + (r0+g)*HS + kb + 2*tig + 8);
        qf[k][3] = *(const unsigned*)(Qs + (r0+g+8)*HS + kb + 2*tig + 8);
    }
    __syncthreads();

    float o[8][4] = {};
    float m0 = -1e30f, m1 = -1e30f, l0 = 0.f, l1 = 0.f;
    int rowA = qr0 + r0 + g;
    int rowB = rowA + 8;
    int wrow_lo = qr0 + r0;
    int wrow_hi = wrow_lo + 15;

    int nchunk = 2 * (qblk + 1);
    attn5_issue(smh, 0, 0, tid, kbase, vtbase);
    CPCOMMIT();

    for (int c = 0; c < nchunk; c++) {
        int s0 = c * 64;
        if (c + 1 < nchunk) {
            attn5_issue(smh, (c+1) & 1, s0 + 64, tid, kbase, vtbase);
            CPCOMMIT();
            CPWAIT(1);
        } else {
            CPWAIT(0);
        }
        __syncthreads();

        if (s0 <= wrow_hi) {
            __half* Ks = smh + (c & 1)*AKVH;
            __half* Vs = Ks + 64*HS;

            float sacc[8][4] = {};
            #pragma unroll
            for (int k = 0; k < 4; k++) {
                int kb = k*16;
                #pragma unroll
                for (int nt = 0; nt < 8; nt++) {
                    const __half* kr = Ks + (nt*8+g)*HS + kb + 2*tig;
                    unsigned b0 = *(const unsigned*)(kr);
                    unsigned b1 = *(const unsigned*)(kr + 8);
                    MMA_F16(sacc[nt], qf[k], b0, b1);
                }
            }

            bool needmask = (s0 + 63 > wrow_lo);
            if (needmask) {
                #pragma unroll
                for (int nt = 0; nt < 8; nt++) {
                    int col0 = s0 + nt*8 + tig*2;
                    if (col0     > rowA) sacc[nt][0] = -1e30f;
                    if (col0 + 1 > rowA) sacc[nt][1] = -1e30f;
                    if (col0     > rowB) sacc[nt][2] = -1e30f;
                    if (col0 + 1 > rowB) sacc[nt][3] = -1e30f;
                }
            }

            float rm0 = -1e30f, rm1 = -1e30f;
            #pragma unroll
            for (int nt = 0; nt < 8; nt++) {
                rm0 = fmaxf(rm0, fmaxf(sacc[nt][0], sacc[nt][1]));
                rm1 = fmaxf(rm1, fmaxf(sacc[nt][2], sacc[nt][3]));
            }
            rm0 = fmaxf(rm0, __shfl_xor_sync(0xffffffffu, rm0, 1));
            rm0 = fmaxf(rm0, __shfl_xor_sync(0xffffffffu, rm0, 2));
            rm1 = fmaxf(rm1, __shfl_xor_sync(0xffffffffu, rm1, 1));
            rm1 = fmaxf(rm1, __shfl_xor_sync(0xffffffffu, rm1, 2));
            float mn0 = fmaxf(m0, rm0), mn1 = fmaxf(m1, rm1);
            float c0f = ex2f(m0 - mn0), c1f = ex2f(m1 - mn1);
            m0 = mn0; m1 = mn1;

            float ps0 = 0.f, ps1 = 0.f;
            #pragma unroll
            for (int nt = 0; nt < 8; nt++) {
                float p0 = ex2f(sacc[nt][0] - mn0);
                float p1 = ex2f(sacc[nt][1] - mn0);
                float p2 = ex2f(sacc[nt][2] - mn1);
                float p3 = ex2f(sacc[nt][3] - mn1);
                ps0 += p0 + p1; ps1 += p2 + p3;
                __half2 hA = __floats2half2_rn(p0, p1);
                __half2 hB = __floats2half2_rn(p2, p3);
                int cb = nt*8 + 2*tig;
                *(unsigned*)(Ps + (r0+g)*HS + cb)   = *(unsigned*)&hA;
                *(unsigned*)(Ps + (r0+g+8)*HS + cb) = *(unsigned*)&hB;
            }
            ps0 += __shfl_xor_sync(0xffffffffu, ps0, 1);
            ps0 += __shfl_xor_sync(0xffffffffu, ps0, 2);
            ps1 += __shfl_xor_sync(0xffffffffu, ps1, 1);
            ps1 += __shfl_xor_sync(0xffffffffu, ps1, 2);
            l0 = l0*c0f + ps0;
            l1 = l1*c1f + ps1;

            #pragma unroll
            for (int nt = 0; nt < 8; nt++) {
                o[nt][0] *= c0f; o[nt][1] *= c0f;
                o[nt][2] *= c1f; o[nt][3] *= c1f;
            }
            __syncwarp();

            #pragma unroll
            for (int k = 0; k < 4; k++) {
                int kb = k*16;
                unsigned a[4];
                a[0] = *(const unsigned*)(Ps + (r0+g)*HS + kb + 2*tig);
                a[1] = *(const unsigned*)(Ps + (r0+g+8)*HS + kb + 2*tig);
                a[2] = *(const unsigned*)(Ps + (r0+g)*HS + kb + 2*tig + 8);
                a[3] = *(const unsigned*)(Ps + (r0+g+8)*HS + kb + 2*tig + 8);
                #pragma unroll
                for (int nt = 0; nt < 8; nt++) {
                    const __half* vr = Vs + (nt*8+g)*HS + kb + 2*tig;
                    unsigned b0 = *(const unsigned*)(vr);
                    unsigned b1 = *(const unsigned*)(vr + 8);
                    MMA_F16(o[nt], a, b0, b1);
                }
            }
        }
        __syncthreads();
    }

    int b = bh >> 4, h = bh & 15;
    float i0 = 1.f / l0, i1 = 1.f / l1;
    #pragma unroll
    for (int nt = 0; nt < 8; nt++) {
        int cb = h*64 + nt*8 + tig*2;
        __half2 hA = __floats2half2_rn(o[nt][0]*i0, o[nt][1]*i0);
        __half2 hB = __floats2half2_rn(o[nt][2]*i1, o[nt][3]*i1);
        *(unsigned*)(g_ao2 + ((long)(b*TT + rowA))*EE + cb) = *(unsigned*)&hA;
        *(unsigned*)(g_ao2 + ((long)(b*TT + rowB))*EE + cb) = *(unsigned*)&hB;
    }
}

// ---------------- launch: 8-chunk GRU pipeline, fully chunked tail ---------
extern "C" void kernel_launch(void* const* d_in, const int* in_sizes, int n_in,
                              void* d_out, int out_size)
{
    const float* x     = (const float*)d_in[0];
    const int*   tok   = (const int*)  d_in[1];
    const float* qwih  = (const float*)d_in[2];
    const float* qwhh  = (const float*)d_in[3];
    const float* qlinw = (const float*)d_in[4];
    const float* kwih  = (const float*)d_in[5];
    const float* kwhh  = (const float*)d_in[6];
    const float* klinw = (const float*)d_in[7];
    const float* vemb  = (const float*)d_in[8];
    const float* qlnw  = (const float*)d_in[9];
    const float* qlnb  = (const float*)d_in[10];
    const float* klnw  = (const float*)d_in[11];
    const float* klnb  = (const float*)d_in[12];
    const float* outw  = (const float*)d_in[13];
    const float* outb  = (const float*)d_in[14];
    float* out = (float*)d_out;

    static cudaStream_t s1 = nullptr;
    static cudaEvent_t evA = nullptr;
    static cudaEvent_t evC[NCHK] = {};
    if (!s1) {
        int lo, hi;
        cudaDeviceGetStreamPriorityRange(&lo, &hi);
        cudaStreamCreateWithPriority(&s1, cudaStreamNonBlocking, hi);
        cudaEventCreateWithFlags(&evA, cudaEventDisableTiming);
        for (int i = 0; i < NCHK; i++)
            cudaEventCreateWithFlags(&evC[i], cudaEventDisableTiming);
        cudaFuncSetAttribute(attn5_kernel,
                             cudaFuncAttributeMaxDynamicSharedMemorySize, ATT5_SMEM);
        cudaFuncSetAttribute(gru_kernel,
                             cudaFuncAttributeMaxDynamicSharedMemorySize, GRU_PAD_SMEM);
    }

    prep_xw_kernel<<<NROW, 256>>>(x, qwih, kwih);                   // #1
    cudaEventRecord(evA, 0);
    hconv_kernel<<<dim3(1024, 3), 256>>>(qlinw, klinw, outw);       // #2
    prep_main_kernel<<<NROW, 256>>>(x, tok, vemb);                  // #3
    cudaStreamWaitEvent(s1, evA, 0);
    // GRU 8-chunk pipeline on s1 (exclusive SMs via smem pad)
    for (int c = 0; c < NCHK; c++) {
        gru_kernel<<<4, 128, GRU_PAD_SMEM, s1>>>(qwhh, kwhh, c);    // c==0 is #4 (profiled)
        cudaEventRecord(evC[c], s1);
    }

    hgemm_qk_kernel<<<dim3(EE/128, NROW/128, 2), 256>>>(x);         // overlaps GRU
    vt_kernel<<<dim3(TT/64, BB*HN), 256>>>();

    for (int c = 0; c < NCHK; c++) {
        cudaStreamWaitEvent(0, evC[c], 0);
        posgemm_kernel<<<dim3(8, 16, 2), 256>>>(qlinw, klinw, c);
        ln_kernel<<<1024, 256>>>(qlnw, qlnb, klnw, klnb, c);
        attn5_kernel<<<dim3(2, BB*HN), 256, ATT5_SMEM>>>(c*2);
        hgemm_out_kernel<<<dim3(EE/128, 4), 256>>>(outb, out, c);
    }
}

// round 14
// speedup vs baseline: 1.1968x; 1.1968x over previous
#include <cuda_runtime.h>
#include <cuda_fp16.h>
#include <math.h>

#define EE 1024
#define HN 16
#define HDIM 64
#define DI 64
#define BB 2
#define TT 2048
#define NROW (BB*TT)   // 4096
#define G3 192
#define KP 960         // proj K
#define NCHK 4         // GRU pipeline chunks
#define TCH (TT/NCHK)  // 512 steps per chunk

// ---------------- scratch (static device memory) ---------------------------
__device__ __half g_proj2[NROW*KP];     // half, shared by q/k
__device__ float g_xw_q[NROW*G3];
__device__ float g_xw_k[NROW*G3];
__device__ float g_pos_q[NROW*DI];
__device__ float g_pos_k[NROW*DI];
__device__ float g_hstate[4*DI];        // GRU h carry between chunk kernels
__device__ float g_qpre[NROW*EE];
__device__ float g_kpre[NROW*EE];
__device__ __half g_qh2[BB*HN*TT*HDIM]; // [bh][t][d], pre-scaled 0.25*log2e
__device__ __half g_kh2[BB*HN*TT*HDIM];
__device__ __half g_vh2[BB*HN*TT*HDIM];
__device__ __half g_vT2[BB*HN*HDIM*TT]; // [bh][d][t]
__device__ __half g_ao2[NROW*EE];       // attention out (half)
__device__ __half g_wq2[EE*EE];         // half weights
__device__ __half g_wk2[EE*EE];
__device__ __half g_wo2[EE*EE];
// split-KV partials for final chunk (rows 1536..2047 per batch)
__device__ float g_pm[2][BB*HN][512];
__device__ float g_pl[2][BB*HN][512];
__device__ float g_po[2][BB*HN][512*64];

__device__ __forceinline__ float ex2f(float x) {
    float y;
    asm("ex2.approx.f32 %0, %1;" : "=f"(y) : "f"(x));
    return y;
}
__device__ __forceinline__ float tanhf_fast(float x) {
    float y;
    asm("tanh.approx.f32 %0, %1;" : "=f"(y) : "f"(x));
    return y;
}
#define LOG2E_F 1.44269504f
#define QSCALE (0.25f*LOG2E_F)

#define MMA_F16(d, a, b0, b1) \
    asm volatile("mma.sync.aligned.m16n8k16.row.col.f32.f16.f16.f32 " \
        "{%0,%1,%2,%3},{%4,%5,%6,%7},{%8,%9},{%0,%1,%2,%3};" \
        : "+f"((d)[0]), "+f"((d)[1]), "+f"((d)[2]), "+f"((d)[3]) \
        : "r"((a)[0]), "r"((a)[1]), "r"((a)[2]), "r"((a)[3]), "r"(b0), "r"(b1))

#define CPA16(dst_u32, src) \
    asm volatile("cp.async.cg.shared.global [%0], [%1], 16;" :: "r"(dst_u32), "l"(src))
#define CPCOMMIT() asm volatile("cp.async.commit_group;")
#define CPWAIT(n)  asm volatile("cp.async.wait_group %0;" :: "n"(n))

// packed f32x2 helpers
__device__ __forceinline__ unsigned long long packf2(float x, float y) {
    unsigned long long p;
    asm("mov.b64 %0, {%1, %2};" : "=l"(p) : "f"(x), "f"(y));
    return p;
}
__device__ __forceinline__ void unpackf2(unsigned long long p, float& x, float& y) {
    asm("mov.b64 {%0, %1}, %2;" : "=f"(x), "=f"(y) : "l"(p));
}
#define FMA2(acc, a, b) \
    asm("fma.rn.f32x2 %0, %1, %2, %0;" : "+l"(acc) : "l"(a), "l"(b))

// ---------------- weight convert to half ------------------------------------
__global__ void __launch_bounds__(256) hconv_kernel(
    const float* __restrict__ qw, const float* __restrict__ kw,
    const float* __restrict__ ow)
{
    const float* src = blockIdx.y == 0 ? qw : (blockIdx.y == 1 ? kw : ow);
    __half* dst = blockIdx.y == 0 ? g_wq2 : (blockIdx.y == 1 ? g_wk2 : g_wo2);
    long i = ((long)blockIdx.x*256 + threadIdx.x)*4;
    float4 v = *(const float4*)(src + i);
    __half2 h01 = __floats2half2_rn(v.x, v.y);
    __half2 h23 = __floats2half2_rn(v.z, v.w);
    uint2 pk;
    pk.x = *(unsigned*)&h01;
    pk.y = *(unsigned*)&h23;
    *(uint2*)(dst + i) = pk;
}

// ---------------- prep_xw: pool(x) @ wih^T for both paths ------------------
__global__ void __launch_bounds__(256) prep_xw_kernel(
    const float* __restrict__ x,
    const float* __restrict__ qwih, const float* __restrict__ kwih)
{
    __shared__ float xs[DI];
    int row = blockIdx.x;
    int tid = threadIdx.x;
    if (tid < DI) {
        const float* xp = x + (long)row*EE + tid*16;
        float s = 0.f;
        #pragma unroll
        for (int i = 0; i < 4; i++) {
            float4 v = ((const float4*)xp)[i];
            s += (v.x + v.y) + (v.z + v.w);
        }
        xs[tid] = s * (1.f/16.f);
    }
    __syncthreads();

    for (int idx = tid; idx < 2*G3; idx += 256) {
        int path = idx / G3, g = idx - path*G3;
        const float* w = (path ? kwih : qwih) + g*DI;
        float a0=0.f, a1=0.f, a2=0.f, a3=0.f;
        #pragma unroll
        for (int d = 0; d < DI; d += 4) {
            a0 += xs[d+0]*w[d+0];
            a1 += xs[d+1]*w[d+1];
            a2 += xs[d+2]*w[d+2];
            a3 += xs[d+3]*w[d+3];
        }
        float acc = (a0+a1)+(a2+a3);
        (path ? g_xw_k : g_xw_q)[(long)row*G3 + g] = acc;
    }
}

// ---------------- prep_main: v = silu(x)*emb (half), proj pool (half) ------
__global__ void __launch_bounds__(256) prep_main_kernel(
    const float* __restrict__ x, const int* __restrict__ tok,
    const float* __restrict__ vemb)
{
    __shared__ float xsh[EE];
    int row = blockIdx.x;
    int tid = threadIdx.x;
    int b = row >> 11, t = row & (TT-1);

    ((float4*)xsh)[tid] = ((const float4*)(x + (long)row*EE))[tid];
    __syncthreads();

    int tk = tok[row];
    const float* ve = vemb + (long)tk*EE;
    for (int c = tid; c < EE; c += 256) {
        float xc = xsh[c];
        float sg = fmaf(0.5f, tanhf_fast(0.5f*xc), 0.5f);
        float val = xc * sg * ve[c];
        int h = c >> 6, d = c & 63;
        g_vh2[((long)(b*HN + h)*TT + t)*HDIM + d] = __float2half_rn(val);
    }

    for (int j = tid; j < KP; j += 256) {
        int s0 = (j*16)/15;
        int e0 = ((j+1)*16 + 14)/15;
        float s = 0.f;
        for (int c = s0; c < e0; c++) s += xsh[c];
        s *= 1.f/(float)(e0 - s0);
        g_proj2[(long)row*KP + j] = __float2half_rn(s);
    }
}

// ---------------- vt: transpose V [bh][t][d] -> [bh][d][t] ------------------
__global__ void __launch_bounds__(256) vt_kernel()
{
    __shared__ __half T[64*72];
    int bh = blockIdx.y;
    int t0 = blockIdx.x * 64;
    int tid = threadIdx.x;

    #pragma unroll
    for (int i = 0; i < 2; i++) {
        int f = tid + i*256;
        int rr = f >> 3;
        int c8 = (f & 7) * 8;
        uint4 v = *(const uint4*)(g_vh2 + ((long)bh*TT + t0 + rr)*HDIM + c8);
        const __half* hv = (const __half*)&v;
        #pragma unroll
        for (int j = 0; j < 8; j++)
            T[(c8 + j)*72 + rr] = hv[j];
    }
    __syncthreads();
    #pragma unroll
    for (int i = 0; i < 2; i++) {
        int f = tid + i*256;
        int rr = f >> 3;
        int c8 = (f & 7) * 8;
        uint4 v = *(const uint4*)(T + rr*72 + c8);
        *(uint4*)(g_vT2 + ((long)bh*HDIM + rr)*TT + t0 + c8) = v;
    }
}

// ---------------- GRU chunk kernel: 512 steps, h carried via g_hstate ------
#define GRU_SPC 32
#define GRU_CHUNK (GRU_SPC*G3)          // 6144 floats
#define GRU_PAD_SMEM 196608             // 192KB: keeps other blocks off these SMs

__global__ void __launch_bounds__(128, 1) gru_kernel(
    const float* __restrict__ qwhh, const float* __restrict__ kwhh, int chunk)
{
    extern __shared__ float gsm[];      // only first 2*GRU_CHUNK used
    __shared__ float hbuf[2][DI];
    int path = blockIdx.x >> 1;
    int b = blockIdx.x & 1;
    int tid = threadIdx.x;
    int j = tid >> 1;
    int half = tid & 1;
    const float* W = (path ? kwhh : qwhh);
    const float* xw = (path ? g_xw_k : g_xw_q) + (long)b*TT*G3 + (long)chunk*TCH*G3;
    float* pos = (path ? g_pos_k : g_pos_q) + (long)b*TT*DI + (long)chunk*TCH*DI;

    unsigned long long wr[16], wz[16], wn[16];
    {
        const float* pr = W + (long)j*DI + half*32;
        const float* pz = W + (long)(64+j)*DI + half*32;
        const float* pn = W + (long)(128+j)*DI + half*32;
        #pragma unroll
        for (int i = 0; i < 16; i++) {
            wr[i] = packf2(pr[2*i], pr[2*i+1]);
            wz[i] = packf2(pz[2*i], pz[2*i+1]);
            wn[i] = packf2(pn[2*i], pn[2*i+1]);
        }
    }

    float h0 = (chunk == 0) ? 0.f : g_hstate[blockIdx.x*DI + j];
    if (tid < DI)
        hbuf[0][tid] = (chunk == 0) ? 0.f : g_hstate[blockIdx.x*DI + tid];
    float hprev = h0;

    #pragma unroll
    for (int i = 0; i < 12; i++) {
        int f = tid + i*128;
        unsigned d = (unsigned)__cvta_generic_to_shared(gsm + f*4);
        CPA16(d, xw + f*4);
    }
    CPCOMMIT();

    const int NC = TCH / GRU_SPC;   // 16
    for (int c = 0; c < NC; c++) {
        if (c + 1 < NC) {
            const float* src = xw + (long)(c+1)*GRU_CHUNK;
            float* dstb = gsm + ((c+1) & 1)*GRU_CHUNK;
            #pragma unroll
            for (int i = 0; i < 12; i++) {
                int f = tid + i*128;
                unsigned d = (unsigned)__cvta_generic_to_shared(dstb + f*4);
                CPA16(d, src + f*4);
            }
            CPCOMMIT();
            CPWAIT(1);
        } else {
            CPWAIT(0);
        }
        __syncthreads();

        const float* xc = gsm + (c & 1)*GRU_CHUNK;
        for (int s = 0; s < GRU_SPC; s++) {
            int t = c*GRU_SPC + s;
            int cur = t & 1, nxt = cur ^ 1;

            float xr = xc[s*G3 + j];
            float xz = xc[s*G3 + 64 + j];
            float xn = xc[s*G3 + 128 + j];

            const float4* hb4 = (const float4*)(hbuf[cur] + half*32);
            unsigned long long ar[4] = {0,0,0,0};
            unsigned long long az[4] = {0,0,0,0};
            unsigned long long an[4] = {0,0,0,0};
            #pragma unroll
            for (int i = 0; i < 8; i++) {
                float4 hv = hb4[i];
                unsigned long long h01 = packf2(hv.x, hv.y);
                unsigned long long h23 = packf2(hv.z, hv.w);
                int e = (i & 1) << 1;
                FMA2(ar[e],   h01, wr[2*i]);  FMA2(ar[e+1], h23, wr[2*i+1]);
                FMA2(az[e],   h01, wz[2*i]);  FMA2(az[e+1], h23, wz[2*i+1]);
                FMA2(an[e],   h01, wn[2*i]);  FMA2(an[e+1], h23, wn[2*i+1]);
            }
            float a0,a1,a2,a3,b0,b1,b2,b3;
            unpackf2(ar[0],a0,a1); unpackf2(ar[1],a2,a3);
            unpackf2(ar[2],b0,b1); unpackf2(ar[3],b2,b3);
            float pr = ((a0+a1)+(a2+a3)) + ((b0+b1)+(b2+b3));
            unpackf2(az[0],a0,a1); unpackf2(az[1],a2,a3);
            unpackf2(az[2],b0,b1); unpackf2(az[3],b2,b3);
            float pz = ((a0+a1)+(a2+a3)) + ((b0+b1)+(b2+b3));
            unpackf2(an[0],a0,a1); unpackf2(an[1],a2,a3);
            unpackf2(an[2],b0,b1); unpackf2(an[3],b2,b3);
            float pn = ((a0+a1)+(a2+a3)) + ((b0+b1)+(b2+b3));

            pr += __shfl_xor_sync(0xffffffffu, pr, 1);
            pz += __shfl_xor_sync(0xffffffffu, pz, 1);
            pn += __shfl_xor_sync(0xffffffffu, pn, 1);

            float r = fmaf(0.5f, tanhf_fast(0.5f*(pr + xr)), 0.5f);
            float z = fmaf(0.5f, tanhf_fast(0.5f*(pz + xz)), 0.5f);
            float n = tanhf_fast(fmaf(r, pn, xn));
            float hn = fmaf(z, hprev - n, n);
            hprev = hn;

            hbuf[nxt][j] = hn;
            if (half == 0) pos[(long)t*DI + j] = hn;
            __syncthreads();
        }
    }

    if (half == 0) g_hstate[blockIdx.x*DI + j] = hprev;
}

// ---------------- fp16 tensor-core GEMM: C = A @ W^T (+res)(+bias) ---------
#define HGS 40
template<bool RES, bool BIAS>
__device__ __forceinline__ void hgemm_body(
    const __half* __restrict__ A, int lda,
    const __half* __restrict__ W, int ldw,
    const float* __restrict__ res, const float* __restrict__ bias,
    float* __restrict__ C, int N, int NK, int m0, int n0)
{
    __shared__ __half As[2][128*HGS];
    __shared__ __half Bs[2][128*HGS];
    int tid = threadIdx.x;
    int wid = tid >> 5, lane = tid & 31;
    int g = lane >> 2, tig = lane & 3;
    int wm = (wid >> 2) * 64, wn = (wid & 3) * 32;
    int lrow = tid >> 1, lc = (tid & 1) * 16;

    const __half* Ap = A + (long)(m0 + lrow)*lda + lc;
    const __half* Wp = W + (long)(n0 + lrow)*ldw + lc;

    uint4 ra0 = *(const uint4*)(Ap);
    uint4 ra1 = *(const uint4*)(Ap + 8);
    uint4 rb0 = *(const uint4*)(Wp);
    uint4 rb1 = *(const uint4*)(Wp + 8);

    float acc[4][4][4] = {};
    int buf = 0;
    for (int kt = 0; kt < NK; kt++) {
        __half* Asb = As[buf];
        __half* Bsb = Bs[buf];
        *(uint4*)(Asb + lrow*HGS + lc) = ra0;
        *(uint4*)(Asb + lrow*HGS + lc + 8) = ra1;
        *(uint4*)(Bsb + lrow*HGS + lc) = rb0;
        *(uint4*)(Bsb + lrow*HGS + lc + 8) = rb1;
        __syncthreads();
        if (kt + 1 < NK) {
            int ko = (kt+1)*32;
            ra0 = *(const uint4*)(Ap + ko);
            ra1 = *(const uint4*)(Ap + ko + 8);
            rb0 = *(const uint4*)(Wp + ko);
            rb1 = *(const uint4*)(Wp + ko + 8);
        }
        #pragma unroll
        for (int kk = 0; kk < 32; kk += 16) {
            unsigned a[4][4], b[4][2];
            #pragma unroll
            for (int mt = 0; mt < 4; mt++) {
                int r = wm + mt*16 + g;
                a[mt][0] = *(const unsigned*)(Asb + r*HGS + kk + 2*tig);
                a[mt][1] = *(const unsigned*)(Asb + (r+8)*HGS + kk + 2*tig);
                a[mt][2] = *(const unsigned*)(Asb + r*HGS + kk + 2*tig + 8);
                a[mt][3] = *(const unsigned*)(Asb + (r+8)*HGS + kk + 2*tig + 8);
            }
            #pragma unroll
            for (int nt = 0; nt < 4; nt++) {
                int r = wn + nt*8 + g;
                b[nt][0] = *(const unsigned*)(Bsb + r*HGS + kk + 2*tig);
                b[nt][1] = *(const unsigned*)(Bsb + r*HGS + kk + 2*tig + 8);
            }
            #pragma unroll
            for (int mt = 0; mt < 4; mt++)
                #pragma unroll
                for (int nt = 0; nt < 4; nt++)
                    MMA_F16(acc[mt][nt], a[mt], b[nt][0], b[nt][1]);
        }
        buf ^= 1;
    }

    #pragma unroll
    for (int mt = 0; mt < 4; mt++) {
        #pragma unroll
        for (int nt = 0; nt < 4; nt++) {
            long r0 = m0 + wm + mt*16 + g;
            long r1 = r0 + 8;
            long cb = n0 + wn + nt*8 + tig*2;
            float v0 = acc[mt][nt][0], v1 = acc[mt][nt][1];
            float v2 = acc[mt][nt][2], v3 = acc[mt][nt][3];
            if (RES) {
                float2 e0 = *(const float2*)(res + r0*N + cb);
                float2 e1 = *(const float2*)(res + r1*N + cb);
                v0 += e0.x; v1 += e0.y; v2 += e1.x; v3 += e1.y;
            }
            if (BIAS) {
                v0 += bias[cb]; v1 += bias[cb+1];
                v2 += bias[cb]; v3 += bias[cb+1];
            }
            *(float2*)(C + r0*N + cb) = make_float2(v0, v1);
            *(float2*)(C + r1*N + cb) = make_float2(v2, v3);
        }
    }
}

__global__ void __launch_bounds__(256) hgemm_qk_kernel(const float* __restrict__ x)
{
    int z = blockIdx.z;
    hgemm_body<true,false>(g_proj2, KP, (z ? g_wk2 : g_wq2) + DI, EE, x, nullptr,
                           z ? g_kpre : g_qpre, EE, KP/32,
                           blockIdx.y*128, blockIdx.x*128);
}

// out-GEMM for one chunk's rows: grid (8, 8); y: b*4 + i (4 M-tiles/batch)
__global__ void __launch_bounds__(256) hgemm_out_kernel(
    const float* __restrict__ bias, float* __restrict__ C, int cch)
{
    int b = blockIdx.y >> 2;
    int m0 = b*TT + cch*TCH + (blockIdx.y & 3)*128;
    hgemm_body<false,true>(g_ao2, EE, g_wo2, EE, nullptr, bias, C, EE, EE/32,
                           m0, blockIdx.x*128);
}

// ---------------- pos small GEMM (chunked): C += pos @ Wpos^T ---------------
// grid (8, 32, 2): per chunk, 2 batches x 512 rows (16 blocks of 32 rows each).
__global__ void __launch_bounds__(256) posgemm_kernel(
    const float* __restrict__ qw, const float* __restrict__ kw, int cch)
{
    int path = blockIdx.z;
    const float* pos = path ? g_pos_k : g_pos_q;
    const float* W = path ? kw : qw;
    float* C = path ? g_kpre : g_qpre;
    __shared__ float Wt[64][132];
    __shared__ float Ps_[32][68];
    int n0 = blockIdx.x * 128;
    int bsel = blockIdx.y >> 4;
    int m0 = bsel*TT + cch*TCH + (blockIdx.y & 15)*32;
    int tid = threadIdx.x;

    for (int i = tid; i < 128*16; i += 256) {
        int r = i >> 4, c4 = (i & 15)*4;
        float4 v = *(const float4*)(W + (long)(n0 + r)*EE + c4);
        Wt[c4+0][r] = v.x; Wt[c4+1][r] = v.y; Wt[c4+2][r] = v.z; Wt[c4+3][r] = v.w;
    }
    for (int i = tid; i < 32*16; i += 256) {
        int r = i >> 4, c4 = (i & 15)*4;
        *(float4*)&Ps_[r][c4] = *(const float4*)(pos + (long)(m0 + r)*DI + c4);
    }
    __syncthreads();

    int tx = tid & 15, ty = tid >> 4;
    int r0 = ty*2, c0 = tx*8;
    float acc[2][8] = {};
    #pragma unroll
    for (int k = 0; k < 64; k++) {
        float p0 = Ps_[r0][k], p1 = Ps_[r0+1][k];
        float4 w0 = *(float4*)&Wt[k][c0];
        float4 w1 = *(float4*)&Wt[k][c0+4];
        acc[0][0] += p0*w0.x; acc[0][1] += p0*w0.y; acc[0][2] += p0*w0.z; acc[0][3] += p0*w0.w;
        acc[0][4] += p0*w1.x; acc[0][5] += p0*w1.y; acc[0][6] += p0*w1.z; acc[0][7] += p0*w1.w;
        acc[1][0] += p1*w0.x; acc[1][1] += p1*w0.y; acc[1][2] += p1*w0.z; acc[1][3] += p1*w0.w;
        acc[1][4] += p1*w1.x; acc[1][5] += p1*w1.y; acc[1][6] += p1*w1.z; acc[1][7] += p1*w1.w;
    }
    #pragma unroll
    for (int i = 0; i < 2; i++) {
        long m = m0 + r0 + i;
        #pragma unroll
        for (int j = 0; j < 8; j += 4) {
            float4 old = *(float4*)(C + m*EE + n0 + c0 + j);
            old.x += acc[i][j]; old.y += acc[i][j+1];
            old.z += acc[i][j+2]; old.w += acc[i][j+3];
            *(float4*)(C + m*EE + n0 + c0 + j) = old;
        }
    }
}

// ---------------- LayerNorm (chunked) -> head-major half --------------------
// grid 2048: path(2) x batch(2) x 512 rows of chunk c.
__global__ void __launch_bounds__(256) ln_kernel(
    const float* __restrict__ wq, const float* __restrict__ bq,
    const float* __restrict__ wk, const float* __restrict__ bk, int cch)
{
    int idx = blockIdx.x;
    int path = idx >> 10;
    int local = idx & 1023;
    int b = local >> 9;
    int t = cch*TCH + (local & 511);
    int row = b*TT + t;
    const float* src = (path ? g_kpre : g_qpre) + (long)row*EE;
    const float* w = path ? wk : wq;
    const float* bb = path ? bk : bq;
    __half* dst = path ? g_kh2 : g_qh2;
    float oscale = path ? 1.f : QSCALE;
    int tid = threadIdx.x;

    float4 v = ((const float4*)src)[tid];
    float s  = v.x + v.y + v.z + v.w;
    float sq = v.x*v.x + v.y*v.y + v.z*v.z + v.w*v.w;
    #pragma unroll
    for (int o = 16; o; o >>= 1) {
        s  += __shfl_xor_sync(0xffffffffu, s,  o);
        sq += __shfl_xor_sync(0xffffffffu, sq, o);
    }
    __shared__ float ss[8], sqs[8];
    __shared__ float mu_s, r_s;
    if ((tid & 31) == 0) { ss[tid >> 5] = s; sqs[tid >> 5] = sq; }
    __syncthreads();
    if (tid == 0) {
        float S = 0.f, SQ = 0.f;
        #pragma unroll
        for (int i = 0; i < 8; i++) { S += ss[i]; SQ += sqs[i]; }
        float mu = S * (1.f/EE);
        float var = SQ * (1.f/EE) - mu*mu;
        mu_s = mu;
        r_s = rsqrtf(var + 1e-5f);
    }
    __syncthreads();
    float mu = mu_s, r = r_s;
    int c0 = tid * 4;
    int h = c0 >> 6, d = c0 & 63;
    float o0 = ((v.x - mu)*r*w[c0+0] + bb[c0+0]) * oscale;
    float o1 = ((v.y - mu)*r*w[c0+1] + bb[c0+1]) * oscale;
    float o2 = ((v.z - mu)*r*w[c0+2] + bb[c0+2]) * oscale;
    float o3 = ((v.w - mu)*r*w[c0+3] + bb[c0+3]) * oscale;
    __half2 h01 = __floats2half2_rn(o0, o1);
    __half2 h23 = __floats2half2_rn(o2, o3);
    uint2 pk;
    pk.x = *(unsigned*)&h01;
    pk.y = *(unsigned*)&h23;
    *(uint2*)&dst[((long)(b*HN + h)*TT + t)*HDIM + d] = pk;
}

// ---------------- fp16 flash attention core (shared by both variants) ------
#define HS 72
#define AKVH (64*HS*2)
#define APSH (2*AKVH)
#define ATT5_SMEM ((APSH + 128*HS)*2)  // 55296 bytes

__device__ __forceinline__ void attn5_issue(
    __half* sm, int buf, int s0, int tid,
    const __half* kb, const __half* vtb)
{
    __half* K = sm + buf*AKVH;
    __half* V = K + 64*HS;
    #pragma unroll
    for (int i = 0; i < 2; i++) {
        int f = tid + i*256;
        int rr = f >> 3;
        int c = (f & 7) * 8;
        unsigned kd = (unsigned)__cvta_generic_to_shared(K + rr*HS + c);
        CPA16(kd, kb + (long)(s0 + rr)*HDIM + c);
        unsigned vd = (unsigned)__cvta_generic_to_shared(V + rr*HS + c);
        CPA16(vd, vtb + (long)rr*TT + s0 + c);
    }
}

// core: processes KV chunks [c_lo, c_hi) for q-block qblk; returns o/m/l.
struct AttnState {
    float o[8][4];
    float m0, m1, l0, l1;
};

__device__ __forceinline__ void attn5_core(
    AttnState& st, __half* smh, int bh, int qblk, int c_lo, int c_hi,
    int tid, int wid, int g, int tig)
{
    __half* Qs = smh;
    __half* Ps = smh + APSH;
    int qr0 = qblk * 128;
    int r0 = wid * 16;

    const __half* qbase = g_qh2 + (long)bh*TT*HDIM;
    const __half* kbase = g_kh2 + (long)bh*TT*HDIM;
    const __half* vtbase = g_vT2 + (long)bh*HDIM*TT;

    #pragma unroll
    for (int i = 0; i < 4; i++) {
        int f = tid + i*256;
        int rr = f >> 3;
        int c = (f & 7) * 8;
        *(uint4*)(Qs + rr*HS + c) =
            *(const uint4*)(qbase + (long)(qr0 + rr)*HDIM + c);
    }
    __syncthreads();
    unsigned qf[4][4];
    #pragma unroll
    for (int k = 0; k < 4; k++) {
        int kb = k*16;
        qf[k][0] = *(const unsigned*)(Qs + (r0+g)*HS + kb + 2*tig);
        qf[k][1] = *(const unsigned*)(Qs + (r0+g+8)*HS + kb + 2*tig);
        qf[k][2] = *(const unsigned*)(Qs + (r0+g)*HS + kb + 2*tig + 8);
        qf[k][3] = *(const unsigned*)(Qs + (r0+g+8)*HS + kb + 2*tig + 8);
    }
    __syncthreads();

    #pragma unroll
    for (int nt = 0; nt < 8; nt++)
        st.o[nt][0] = st.o[nt][1] = st.o[nt][2] = st.o[nt][3] = 0.f;
    st.m0 = -1e30f; st.m1 = -1e30f; st.l0 = 0.f; st.l1 = 0.f;

    int rowA = qr0 + r0 + g;
    int rowB = rowA + 8;
    int wrow_lo = qr0 + r0;
    int wrow_hi = wrow_lo + 15;

    attn5_issue(smh, 0, c_lo*64, tid, kbase, vtbase);
    CPCOMMIT();

    for (int c = c_lo; c < c_hi; c++) {
        int s0 = c * 64;
        int buf = (c - c_lo) & 1;
        if (c + 1 < c_hi) {
            attn5_issue(smh, buf ^ 1, s0 + 64, tid, kbase, vtbase);
            CPCOMMIT();
            CPWAIT(1);
        } else {
            CPWAIT(0);
        }
        __syncthreads();

        if (s0 <= wrow_hi) {
            __half* Ks = smh + buf*AKVH;
            __half* Vs = Ks + 64*HS;

            float sacc[8][4] = {};
            #pragma unroll
            for (int k = 0; k < 4; k++) {
                int kb = k*16;
                #pragma unroll
                for (int nt = 0; nt < 8; nt++) {
                    const __half* kr = Ks + (nt*8+g)*HS + kb + 2*tig;
                    unsigned b0 = *(const unsigned*)(kr);
                    unsigned b1 = *(const unsigned*)(kr + 8);
                    MMA_F16(sacc[nt], qf[k], b0, b1);
                }
            }

            bool needmask = (s0 + 63 > wrow_lo);
            if (needmask) {
                #pragma unroll
                for (int nt = 0; nt < 8; nt++) {
                    int col0 = s0 + nt*8 + tig*2;
                    if (col0     > rowA) sacc[nt][0] = -1e30f;
                    if (col0 + 1 > rowA) sacc[nt][1] = -1e30f;
                    if (col0     > rowB) sacc[nt][2] = -1e30f;
                    if (col0 + 1 > rowB) sacc[nt][3] = -1e30f;
                }
            }

            float rm0 = -1e30f, rm1 = -1e30f;
            #pragma unroll
            for (int nt = 0; nt < 8; nt++) {
                rm0 = fmaxf(rm0, fmaxf(sacc[nt][0], sacc[nt][1]));
                rm1 = fmaxf(rm1, fmaxf(sacc[nt][2], sacc[nt][3]));
            }
            rm0 = fmaxf(rm0, __shfl_xor_sync(0xffffffffu, rm0, 1));
            rm0 = fmaxf(rm0, __shfl_xor_sync(0xffffffffu, rm0, 2));
            rm1 = fmaxf(rm1, __shfl_xor_sync(0xffffffffu, rm1, 1));
            rm1 = fmaxf(rm1, __shfl_xor_sync(0xffffffffu, rm1, 2));
            float mn0 = fmaxf(st.m0, rm0), mn1 = fmaxf(st.m1, rm1);
            float c0f = ex2f(st.m0 - mn0), c1f = ex2f(st.m1 - mn1);
            st.m0 = mn0; st.m1 = mn1;

            float ps0 = 0.f, ps1 = 0.f;
            #pragma unroll
            for (int nt = 0; nt < 8; nt++) {
                float p0 = ex2f(sacc[nt][0] - mn0);
                float p1 = ex2f(sacc[nt][1] - mn0);
                float p2 = ex2f(sacc[nt][2] - mn1);
                float p3 = ex2f(sacc[nt][3] - mn1);
                ps0 += p0 + p1; ps1 += p2 + p3;
                __half2 hA = __floats2half2_rn(p0, p1);
                __half2 hB = __floats2half2_rn(p2, p3);
                int cb = nt*8 + 2*tig;
                *(unsigned*)(Ps + (r0+g)*HS + cb)   = *(unsigned*)&hA;
                *(unsigned*)(Ps + (r0+g+8)*HS + cb) = *(unsigned*)&hB;
            }
            ps0 += __shfl_xor_sync(0xffffffffu, ps0, 1);
            ps0 += __shfl_xor_sync(0xffffffffu, ps0, 2);
            ps1 += __shfl_xor_sync(0xffffffffu, ps1, 1);
            ps1 += __shfl_xor_sync(0xffffffffu, ps1, 2);
            st.l0 = st.l0*c0f + ps0;
            st.l1 = st.l1*c1f + ps1;

            #pragma unroll
            for (int nt = 0; nt < 8; nt++) {
                st.o[nt][0] *= c0f; st.o[nt][1] *= c0f;
                st.o[nt][2] *= c1f; st.o[nt][3] *= c1f;
            }
            __syncwarp();

            #pragma unroll
            for (int k = 0; k < 4; k++) {
                int kb = k*16;
                unsigned a[4];
                a[0] = *(const unsigned*)(Ps + (r0+g)*HS + kb + 2*tig);
                a[1] = *(const unsigned*)(Ps + (r0+g+8)*HS + kb + 2*tig);
                a[2] = *(const unsigned*)(Ps + (r0+g)*HS + kb + 2*tig + 8);
                a[3] = *(const unsigned*)(Ps + (r0+g+8)*HS + kb + 2*tig + 8);
                #pragma unroll
                for (int nt = 0; nt < 8; nt++) {
                    const __half* vr = Vs + (nt*8+g)*HS + kb + 2*tig;
                    unsigned b0 = *(const unsigned*)(vr);
                    unsigned b1 = *(const unsigned*)(vr + 8);
                    MMA_F16(st.o[nt], a, b0, b1);
                }
            }
        }
        __syncthreads();
    }
}

// normal attention (chunks 0..2): writes normalized half output
__global__ void __launch_bounds__(256, 2) attn5_kernel(int qb_base)
{
    extern __shared__ __half smh[];
    int bh = blockIdx.y;
    int qblk = qb_base + (int)gridDim.x - 1 - (int)blockIdx.x;
    int tid = threadIdx.x;
    int wid = tid >> 5, lane = tid & 31;
    int g = lane >> 2, tig = lane & 3;

    AttnState st;
    attn5_core(st, smh, bh, qblk, 0, 2*(qblk+1), tid, wid, g, tig);

    int qr0 = qblk*128, r0 = wid*16;
    int rowA = qr0 + r0 + g, rowB = rowA + 8;
    int b = bh >> 4, h = bh & 15;
    float i0 = 1.f / st.l0, i1 = 1.f / st.l1;
    #pragma unroll
    for (int nt = 0; nt < 8; nt++) {
        int cb = h*64 + nt*8 + tig*2;
        __half2 hA = __floats2half2_rn(st.o[nt][0]*i0, st.o[nt][1]*i0);
        __half2 hB = __floats2half2_rn(st.o[nt][2]*i1, st.o[nt][3]*i1);
        *(unsigned*)(g_ao2 + ((long)(b*TT + rowA))*EE + cb) = *(unsigned*)&hA;
        *(unsigned*)(g_ao2 + ((long)(b*TT + rowB))*EE + cb) = *(unsigned*)&hB;
    }
}

// split-KV attention for final chunk (qblks 12..15): writes partials
__global__ void __launch_bounds__(256, 2) attn5_split_kernel()
{
    extern __shared__ __half smh[];
    int bh = blockIdx.y;
    int qi = 3 - ((int)blockIdx.x >> 1);   // longest first
    int split = blockIdx.x & 1;
    int qblk = 12 + qi;
    int ctot = 2*(qblk+1);
    int chalf = qblk + 1;
    int c_lo = split ? chalf : 0;
    int c_hi = split ? ctot : chalf;
    int tid = threadIdx.x;
    int wid = tid >> 5, lane = tid & 31;
    int g = lane >> 2, tig = lane & 3;

    AttnState st;
    attn5_core(st, smh, bh, qblk, c_lo, c_hi, tid, wid, g, tig);

    int r0 = wid*16;
    int plA = qi*128 + r0 + g;
    int plB = plA + 8;
    if (tig == 0) {
        g_pm[split][bh][plA] = st.m0; g_pl[split][bh][plA] = st.l0;
        g_pm[split][bh][plB] = st.m1; g_pl[split][bh][plB] = st.l1;
    }
    float* poA = g_po[split][bh] + (long)plA*64;
    float* poB = g_po[split][bh] + (long)plB*64;
    #pragma unroll
    for (int nt = 0; nt < 8; nt++) {
        int cb = nt*8 + 2*tig;
        *(float2*)(poA + cb) = make_float2(st.o[nt][0], st.o[nt][1]);
        *(float2*)(poB + cb) = make_float2(st.o[nt][2], st.o[nt][3]);
    }
}

// merge partials -> g_ao2 for rows 1536..2047 of each batch
__global__ void __launch_bounds__(256) attn_merge_kernel()
{
    int bh = blockIdx.x;           // 0..31
    int rg = blockIdx.y;           // 0..31
    int tid = threadIdx.x;
    int row = rg*16 + (tid >> 4);  // 0..511
    int dg = (tid & 15) * 4;

    float m0 = g_pm[0][bh][row], m1 = g_pm[1][bh][row];
    float l0 = g_pl[0][bh][row], l1 = g_pl[1][bh][row];
    float m = fmaxf(m0, m1);
    float w0 = ex2f(m0 - m), w1 = ex2f(m1 - m);
    float inv = 1.f / fmaf(l0, w0, l1*w1);
    float4 o0 = *(float4*)(g_po[0][bh] + (long)row*64 + dg);
    float4 o1 = *(float4*)(g_po[1][bh] + (long)row*64 + dg);
    float r0 = fmaf(o0.x, w0, o1.x*w1)*inv;
    float r1 = fmaf(o0.y, w0, o1.y*w1)*inv;
    float r2 = fmaf(o0.z, w0, o1.z*w1)*inv;
    float r3 = fmaf(o0.w, w0, o1.w*w1)*inv;
    __half2 hA = __floats2half2_rn(r0, r1);
    __half2 hB = __floats2half2_rn(r2, r3);
    int b = bh >> 4, h = bh & 15;
    int t = 3*TCH + row;           // rows 1536..2047
    uint2 pk;
    pk.x = *(unsigned*)&hA;
    pk.y = *(unsigned*)&hB;
    *(uint2*)(g_ao2 + ((long)(b*TT + t))*EE + h*64 + dg) = pk;
}

// ---------------- launch: 4-chunk GRU pipeline, split-KV final attn --------
extern "C" void kernel_launch(void* const* d_in, const int* in_sizes, int n_in,
                              void* d_out, int out_size)
{
    const float* x     = (const float*)d_in[0];
    const int*   tok   = (const int*)  d_in[1];
    const float* qwih  = (const float*)d_in[2];
    const float* qwhh  = (const float*)d_in[3];
    const float* qlinw = (const float*)d_in[4];
    const float* kwih  = (const float*)d_in[5];
    const float* kwhh  = (const float*)d_in[6];
    const float* klinw = (const float*)d_in[7];
    const float* vemb  = (const float*)d_in[8];
    const float* qlnw  = (const float*)d_in[9];
    const float* qlnb  = (const float*)d_in[10];
    const float* klnw  = (const float*)d_in[11];
    const float* klnb  = (const float*)d_in[12];
    const float* outw  = (const float*)d_in[13];
    const float* outb  = (const float*)d_in[14];
    float* out = (float*)d_out;

    static cudaStream_t s1 = nullptr;
    static cudaEvent_t evA = nullptr;
    static cudaEvent_t evC[NCHK] = {};
    if (!s1) {
        int lo, hi;
        cudaDeviceGetStreamPriorityRange(&lo, &hi);
        cudaStreamCreateWithPriority(&s1, cudaStreamNonBlocking, hi);
        cudaEventCreateWithFlags(&evA, cudaEventDisableTiming);
        for (int i = 0; i < NCHK; i++)
            cudaEventCreateWithFlags(&evC[i], cudaEventDisableTiming);
        cudaFuncSetAttribute(attn5_kernel,
                             cudaFuncAttributeMaxDynamicSharedMemorySize, ATT5_SMEM);
        cudaFuncSetAttribute(attn5_split_kernel,
                             cudaFuncAttributeMaxDynamicSharedMemorySize, ATT5_SMEM);
        cudaFuncSetAttribute(gru_kernel,
                             cudaFuncAttributeMaxDynamicSharedMemorySize, GRU_PAD_SMEM);
    }

    prep_xw_kernel<<<NROW, 256>>>(x, qwih, kwih);                   // #1
    cudaEventRecord(evA, 0);
    hconv_kernel<<<dim3(1024, 3), 256>>>(qlinw, klinw, outw);       // #2
    prep_main_kernel<<<NROW, 256>>>(x, tok, vemb);                  // #3
    cudaStreamWaitEvent(s1, evA, 0);
    // GRU 4-chunk pipeline on s1 (exclusive SMs via smem pad)
    for (int c = 0; c < NCHK; c++) {
        gru_kernel<<<4, 128, GRU_PAD_SMEM, s1>>>(qwhh, kwhh, c);    // c==0 is #4 (profiled)
        cudaEventRecord(evC[c], s1);
    }

    hgemm_qk_kernel<<<dim3(EE/128, NROW/128, 2), 256>>>(x);         // overlaps GRU
    vt_kernel<<<dim3(TT/64, BB*HN), 256>>>();

    for (int c = 0; c < 3; c++) {
        cudaStreamWaitEvent(0, evC[c], 0);
        posgemm_kernel<<<dim3(8, 32, 2), 256>>>(qlinw, klinw, c);
        ln_kernel<<<2048, 256>>>(qlnw, qlnb, klnw, klnb, c);
        attn5_kernel<<<dim3(4, BB*HN), 256, ATT5_SMEM>>>(c*4);
        hgemm_out_kernel<<<dim3(8, 8), 256>>>(outb, out, c);        // hidden
    }
    // final chunk: split-KV attention halves the longest (diagonal) block
    cudaStreamWaitEvent(0, evC[3], 0);
    posgemm_kernel<<<dim3(8, 32, 2), 256>>>(qlinw, klinw, 3);
    ln_kernel<<<2048, 256>>>(qlnw, qlnb, klnw, klnb, 3);
    attn5_split_kernel<<<dim3(8, BB*HN), 256, ATT5_SMEM>>>();
    attn_merge_kernel<<<dim3(32, 32), 256>>>();
    hgemm_out_kernel<<<dim3(8, 8), 256>>>(outb, out, 3);
}